// round 1
// baseline (speedup 1.0000x reference)
#include <cuda_runtime.h>
#include <cuda_bf16.h>

#define B_   16
#define C_   192
#define TX_  512
#define TY_  2048
#define SEG_ 32
#define K2_  384          // 2*C
#define NEG_INF_ (-1e9f)

// ---------------- scratch (device globals: no runtime allocation) ----------------
__device__ float g_B[B_ * K2_ * TX_];        // [b][k][s]: k<192 -> exp(-2 logs); k>=192 -> exp(-2 logs)*m_p
__device__ float g_cvec[B_ * TX_];           // per-column constant term
__device__ float g_negcent[(size_t)B_ * TY_ * TX_];  // 64 MB
__device__ int   g_idx[B_ * TY_];            // chosen path column per row (-1 if t >= t_y)

// ---------------- helpers ----------------
union F2 { float2 f; unsigned long long u; };

__device__ __forceinline__ unsigned long long ffma2(unsigned long long a,
                                                    unsigned long long b,
                                                    unsigned long long c) {
    unsigned long long d;
    asm("fma.rn.f32x2 %0, %1, %2, %3;" : "=l"(d) : "l"(a), "l"(b), "l"(c));
    return d;
}

// ---------------- prep: B matrix ----------------
__global__ void prep_kernel(const float* __restrict__ m_p, const float* __restrict__ logs_p) {
    int i = blockIdx.x * blockDim.x + threadIdx.x;   // over B*C*TX (same layout as m_p/logs_p)
    if (i >= B_ * C_ * TX_) return;
    int s = i % TX_;
    int c = (i / TX_) % C_;
    int b = i / (TX_ * C_);
    float lg = logs_p[i];
    float mp = m_p[i];
    float se = expf(-2.0f * lg);
    g_B[(b * K2_ + c) * TX_ + s]        = se;
    g_B[(b * K2_ + C_ + c) * TX_ + s]   = se * mp;
}

// ---------------- prep: per-column constant ----------------
__global__ void cvec_kernel(const float* __restrict__ m_p, const float* __restrict__ logs_p) {
    int b = blockIdx.x;
    int s = threadIdx.x;                              // 512 threads
    float acc = 0.f;
    for (int c = 0; c < C_; c++) {
        int off = (b * C_ + c) * TX_ + s;
        float lg = logs_p[off];
        float mp = m_p[off];
        float se = expf(-2.0f * lg);
        acc += -0.5f * se * mp * mp - lg;
    }
    g_cvec[b * TX_ + s] = acc;
}

// ---------------- GEMM: neg_cent = A^T B + cvec ----------------
#define BM 128
#define BN 128
#define BK 16

__global__ void __launch_bounds__(256) gemm_kernel(const float* __restrict__ z_p,
                                                   const int* __restrict__ x_lengths,
                                                   const int* __restrict__ y_lengths)
{
    const int b  = blockIdx.z;
    const int m0 = blockIdx.y * BM;
    const int n0 = blockIdx.x * BN;
    if (m0 >= y_lengths[b]) return;     // rows >= t_y never used
    if (n0 >= x_lengths[b]) return;     // cols >= t_x masked in DP

    __shared__ float As[2][BK][BM];
    __shared__ float Bs[2][BK][BN];

    const int tid   = threadIdx.x;
    const int kRow  = tid >> 4;          // 0..15 (load row)
    const int lbase = (tid & 15) << 3;   // 0..120 (load col base, 8 wide)
    const int mBase = (tid >> 4) << 3;   // compute: 8 rows
    const int nBase = (tid & 15) << 3;   // compute: 8 cols

    const float* zpb = z_p + b * C_ * TY_;
    const float* Bb  = g_B + b * K2_ * TX_;

    F2 acc[8][4];
#pragma unroll
    for (int i = 0; i < 8; i++)
#pragma unroll
        for (int j = 0; j < 4; j++) { acc[i][j].f.x = 0.f; acc[i][j].f.y = 0.f; }

    float4 ra0, ra1, rb0, rb1;

    // prologue load (iteration 0)
    {
        int kk = kRow;
        int cA = (kk < C_) ? kk : kk - C_;
        const float* pA = zpb + cA * TY_ + m0 + lbase;
        ra0 = *(const float4*)pA;
        ra1 = *(const float4*)(pA + 4);
        if (kk < C_) {
            ra0.x = -0.5f * ra0.x * ra0.x; ra0.y = -0.5f * ra0.y * ra0.y;
            ra0.z = -0.5f * ra0.z * ra0.z; ra0.w = -0.5f * ra0.w * ra0.w;
            ra1.x = -0.5f * ra1.x * ra1.x; ra1.y = -0.5f * ra1.y * ra1.y;
            ra1.z = -0.5f * ra1.z * ra1.z; ra1.w = -0.5f * ra1.w * ra1.w;
        }
        const float* pB = Bb + kk * TX_ + n0 + lbase;
        rb0 = *(const float4*)pB;
        rb1 = *(const float4*)(pB + 4);
    }
    *(float4*)&As[0][kRow][lbase]     = ra0;
    *(float4*)&As[0][kRow][lbase + 4] = ra1;
    *(float4*)&Bs[0][kRow][lbase]     = rb0;
    *(float4*)&Bs[0][kRow][lbase + 4] = rb1;
    __syncthreads();

    const int NIT = K2_ / BK;   // 24
    for (int it = 0; it < NIT; ++it) {
        const int cur = it & 1;
        if (it + 1 < NIT) {
            int kk = (it + 1) * BK + kRow;
            int cA = (kk < C_) ? kk : kk - C_;
            const float* pA = zpb + cA * TY_ + m0 + lbase;
            ra0 = *(const float4*)pA;
            ra1 = *(const float4*)(pA + 4);
            if (kk < C_) {
                ra0.x = -0.5f * ra0.x * ra0.x; ra0.y = -0.5f * ra0.y * ra0.y;
                ra0.z = -0.5f * ra0.z * ra0.z; ra0.w = -0.5f * ra0.w * ra0.w;
                ra1.x = -0.5f * ra1.x * ra1.x; ra1.y = -0.5f * ra1.y * ra1.y;
                ra1.z = -0.5f * ra1.z * ra1.z; ra1.w = -0.5f * ra1.w * ra1.w;
            }
            const float* pB = Bb + kk * TX_ + n0 + lbase;
            rb0 = *(const float4*)pB;
            rb1 = *(const float4*)(pB + 4);
        }
#pragma unroll
        for (int k = 0; k < BK; k++) {
            float4 a0 = *(const float4*)&As[cur][k][mBase];
            float4 a1 = *(const float4*)&As[cur][k][mBase + 4];
            float4 b0 = *(const float4*)&Bs[cur][k][nBase];
            float4 b1 = *(const float4*)&Bs[cur][k][nBase + 4];
            F2 bb[4];
            bb[0].f = make_float2(b0.x, b0.y);
            bb[1].f = make_float2(b0.z, b0.w);
            bb[2].f = make_float2(b1.x, b1.y);
            bb[3].f = make_float2(b1.z, b1.w);
            float a[8] = {a0.x, a0.y, a0.z, a0.w, a1.x, a1.y, a1.z, a1.w};
#pragma unroll
            for (int i = 0; i < 8; i++) {
                F2 aa; aa.f = make_float2(a[i], a[i]);
#pragma unroll
                for (int j = 0; j < 4; j++)
                    acc[i][j].u = ffma2(aa.u, bb[j].u, acc[i][j].u);
            }
        }
        if (it + 1 < NIT) {
            const int nxt = cur ^ 1;
            *(float4*)&As[nxt][kRow][lbase]     = ra0;
            *(float4*)&As[nxt][kRow][lbase + 4] = ra1;
            *(float4*)&Bs[nxt][kRow][lbase]     = rb0;
            *(float4*)&Bs[nxt][kRow][lbase + 4] = rb1;
        }
        __syncthreads();
    }

    // epilogue: add per-column constant and store
    float4 cv0 = *(const float4*)(g_cvec + b * TX_ + n0 + nBase);
    float4 cv1 = *(const float4*)(g_cvec + b * TX_ + n0 + nBase + 4);
    float* outbase = g_negcent + ((size_t)b * TY_ + m0 + mBase) * TX_ + n0 + nBase;
#pragma unroll
    for (int i = 0; i < 8; i++) {
        float4 o0, o1;
        o0.x = acc[i][0].f.x + cv0.x; o0.y = acc[i][0].f.y + cv0.y;
        o0.z = acc[i][1].f.x + cv0.z; o0.w = acc[i][1].f.y + cv0.w;
        o1.x = acc[i][2].f.x + cv1.x; o1.y = acc[i][2].f.y + cv1.y;
        o1.z = acc[i][3].f.x + cv1.z; o1.w = acc[i][3].f.y + cv1.w;
        float* op = outbase + (size_t)i * TX_;
        *(float4*)op       = o0;
        *(float4*)(op + 4) = o1;
    }
}

// ---------------- MAS DP (forward + fused backtrack) ----------------
__device__ __forceinline__ void dp_load4(float4 (&buf)[4][4], const float* base, int t0, int colbase) {
#pragma unroll
    for (int r = 0; r < 4; r++) {
        const float4* p = (const float4*)(base + (size_t)(t0 + r) * TX_ + colbase);
        buf[r][0] = p[0]; buf[r][1] = p[1]; buf[r][2] = p[2]; buf[r][3] = p[3];
    }
}

__device__ __forceinline__ void dp_rows4(const float4 (&buf)[4][4], float (&v)[16],
                                         unsigned short* dirs, int t0,
                                         int t_x, int colbase, int lane)
{
#pragma unroll
    for (int r = 0; r < 4; r++) {
        const int t = t0 + r;
        float rowv[16];
#pragma unroll
        for (int q = 0; q < 4; q++) {
            rowv[4*q+0] = buf[r][q].x; rowv[4*q+1] = buf[r][q].y;
            rowv[4*q+2] = buf[r][q].z; rowv[4*q+3] = buf[r][q].w;
        }
        float prev = __shfl_up_sync(0xffffffffu, v[15], 1);
        if (lane == 0) prev = NEG_INF_;
        unsigned int bits = 0u;
        float nv[16];
#pragma unroll
        for (int j = 0; j < 16; j++) {
            float left = (j == 0) ? prev : v[j - 1];
            if (left > v[j]) bits |= (1u << j);     // dirn computed on OLD v
            float mx = fmaxf(left, v[j]);
            float t2 = fmaxf(rowv[j] + mx, NEG_INF_);
            nv[j] = ((colbase + j) < t_x) ? t2 : NEG_INF_;
        }
#pragma unroll
        for (int j = 0; j < 16; j++) v[j] = nv[j];
        dirs[t * 32 + lane] = (unsigned short)bits;
    }
}

__global__ void __launch_bounds__(32) dp_kernel(const int* __restrict__ x_lengths,
                                                const int* __restrict__ y_lengths)
{
    extern __shared__ unsigned short dirs[];   // [2048][32] bit-packed directions = 128 KB
    const int b    = blockIdx.x;
    const int lane = threadIdx.x;
    int t_x = min(x_lengths[b], TX_);
    int t_y = min(y_lengths[b], TY_);
    const int colbase = lane * 16;
    const float* base = g_negcent + (size_t)b * TY_ * TX_;

    float v[16];
#pragma unroll
    for (int j = 0; j < 16; j++) v[j] = NEG_INF_;
    if (lane == 0) v[0] = 0.0f;

    const int tEnd = (t_y + 3) & ~3;   // run a few extra rows; their dirs are never read

    float4 bufA[4][4], bufB[4][4];
    dp_load4(bufA, base, 0, colbase);
    for (int t0 = 0; t0 < tEnd; t0 += 8) {
        if (t0 + 4 < tEnd) dp_load4(bufB, base, t0 + 4, colbase);
        dp_rows4(bufA, v, dirs, t0, t_x, colbase, lane);
        if (t0 + 8 < tEnd) dp_load4(bufA, base, t0 + 8, colbase);
        if (t0 + 4 < tEnd) dp_rows4(bufB, v, dirs, t0 + 4, t_x, colbase, lane);
    }

    __syncwarp();

    // rows >= t_y: no path
    for (int t = t_y + lane; t < TY_; t += 32) g_idx[b * TY_ + t] = -1;

    // backtrack (single lane, chain through smem)
    if (lane == 0) {
        int idx = t_x - 1;
        for (int j = t_y - 1; j >= 0; j--) {
            g_idx[b * TY_ + j] = idx;
            unsigned int w = dirs[j * 32 + (idx >> 4)];
            idx -= (int)((w >> (idx & 15)) & 1u);
        }
    }
}

// ---------------- attn output (one-hot rows) ----------------
__global__ void attn_kernel(float* __restrict__ out_attn) {
    const int rowid = blockIdx.x;           // b*2048 + t
    const int idx = g_idx[rowid];
    const int s0 = threadIdx.x * 4;         // 128 threads * 4 = 512
    float4 val = make_float4(0.f, 0.f, 0.f, 0.f);
    if (idx >= s0 && idx < s0 + 4) {
        if (idx == s0)     val.x = 1.f;
        else if (idx == s0 + 1) val.y = 1.f;
        else if (idx == s0 + 2) val.z = 1.f;
        else                    val.w = 1.f;
    }
    *(float4*)(out_attn + (size_t)rowid * TX_ + s0) = val;
}

// ---------------- gathered m_p / logs_p ----------------
__global__ void gather_kernel(const float* __restrict__ m_p, const float* __restrict__ logs_p,
                              float* __restrict__ out_m, float* __restrict__ out_l)
{
    int i = blockIdx.x * blockDim.x + threadIdx.x;  // over B*C*TY
    if (i >= B_ * C_ * TY_) return;
    int t = i % TY_;
    int c = (i / TY_) % C_;
    int b = i / (TY_ * C_);
    int idx = g_idx[b * TY_ + t];
    float vm = 0.f, vl = 0.f;
    if (idx >= 0) {
        int off = (b * C_ + c) * TX_ + idx;
        vm = m_p[off];
        vl = logs_p[off];
    }
    out_m[i] = vm;
    out_l[i] = vl;
}

// ---------------- random segment slice ----------------
__global__ void zslice_kernel(const float* __restrict__ z, const int* __restrict__ y_lengths,
                              const float* __restrict__ rand_u,
                              float* __restrict__ out_z, float* __restrict__ out_ids)
{
    int i = blockIdx.x * blockDim.x + threadIdx.x;  // over B*C*SEG
    if (i >= B_ * C_ * SEG_) return;
    int k = i % SEG_;
    int c = (i / SEG_) % C_;
    int b = i / (SEG_ * C_);
    int safe  = min(y_lengths[b], TY_);
    int idmax = max(safe - SEG_, 0);
    int ids   = (int)(rand_u[b] * ((float)idmax + 1e-8f));
    float vv = z[(b * C_ + c) * TY_ + ids + k];
    out_z[i] = (k < safe - ids) ? vv : 0.f;
    if (i < B_) {
        int sb = min(y_lengths[i], TY_);
        int im = max(sb - SEG_, 0);
        out_ids[i] = (float)((int)(rand_u[i] * ((float)im + 1e-8f)));
    }
}

// ---------------- launcher ----------------
extern "C" void kernel_launch(void* const* d_in, const int* in_sizes, int n_in,
                              void* d_out, int out_size)
{
    const float* z         = (const float*)d_in[0];
    const float* z_p       = (const float*)d_in[1];
    const float* m_p       = (const float*)d_in[2];
    const float* logs_p    = (const float*)d_in[3];
    const int*   x_lengths = (const int*)d_in[4];
    const int*   y_lengths = (const int*)d_in[5];
    const float* rand_u    = (const float*)d_in[6];

    float* out      = (float*)d_out;
    float* out_z    = out;                   // 16*192*32      = 98304
    float* out_ids  = out + 98304;           // 16
    float* out_attn = out + 98320;           // 16*2048*512    = 16777216
    float* out_m    = out + 16875536;        // 16*192*2048    = 6291456
    float* out_l    = out + 23166992;        // 16*192*2048    = 6291456
    (void)in_sizes; (void)n_in; (void)out_size;

    prep_kernel<<<(B_ * C_ * TX_ + 255) / 256, 256>>>(m_p, logs_p);
    cvec_kernel<<<B_, TX_>>>(m_p, logs_p);

    dim3 gg(TX_ / BN, TY_ / BM, B_);
    gemm_kernel<<<gg, 256>>>(z_p, x_lengths, y_lengths);

    cudaFuncSetAttribute(dp_kernel, cudaFuncAttributeMaxDynamicSharedMemorySize, TY_ * 32 * 2);
    dp_kernel<<<B_, 32, TY_ * 32 * 2>>>(x_lengths, y_lengths);

    attn_kernel<<<B_ * TY_, TX_ / 4>>>(out_attn);
    gather_kernel<<<(B_ * C_ * TY_ + 255) / 256, 256>>>(m_p, logs_p, out_m, out_l);
    zslice_kernel<<<(B_ * C_ * SEG_ + 255) / 256, 256>>>(z, y_lengths, rand_u, out_z, out_ids);
}